// round 1
// baseline (speedup 1.0000x reference)
#include <cuda_runtime.h>
#include <cstdint>

// ---------------- problem constants ----------------
#define A_N   8
#define C_N   256
#define S1V   128
#define D1V   128
#define S_TOT (S1V * D1V)     // 16384 tokens per batch row
#define KSEL  2048            // k = CAPACITY * S_TOT
#define NSEL  2047            // n_sel = k - 1
#define LPAD  2048            // padded selected length (s1 * c = 128*16)
#define HH    128             // conv image height
#define WW    16              // conv image width

// ---------------- device scratch (no cudaMalloc allowed) ----------------
__device__ float g_w[A_N * S_TOT];              // router logits
__device__ int   g_idx[A_N * KSEL];             // selected token ids per slot
__device__ int   g_info[A_N * S_TOT];           // per-token: bit31 = masked, low16 = slot+1 (0 = not selected)
__device__ float g_blkin[A_N * C_N * LPAD];     // gathered conv input
__device__ float g_convout[A_N * C_N * LPAD];   // conv output (+bias)

// ======================================================================
// 1) Router: w[a][t] = sum_c x[a][c][t] * rw[c] + rb
//    grid (16, 8), 256 threads, each thread 4 tokens (float4)
// ======================================================================
__global__ void router_kernel(const float* __restrict__ x,
                              const float* __restrict__ rw,
                              const float* __restrict__ rb) {
    __shared__ float srw[C_N];
    int tid = threadIdx.x;
    srw[tid] = rw[tid];
    __syncthreads();

    int a  = blockIdx.y;
    int t0 = (blockIdx.x * 256 + tid) * 4;
    const float4* xp = (const float4*)(x + (size_t)a * C_N * S_TOT + t0);

    float4 acc = make_float4(0.f, 0.f, 0.f, 0.f);
#pragma unroll 8
    for (int c = 0; c < C_N; c++) {
        float4 v = xp[(size_t)c * (S_TOT / 4)];
        float wv = srw[c];
        acc.x += v.x * wv; acc.y += v.y * wv;
        acc.z += v.z * wv; acc.w += v.w * wv;
    }
    float b = rb[0];
    float4 o = make_float4(acc.x + b, acc.y + b, acc.z + b, acc.w + b);
    *(float4*)(g_w + (size_t)a * S_TOT + t0) = o;
}

// ======================================================================
// 2) Select: exact k-th largest (binary search on order-preserving uint
//    keys), strict-greater mask, stable masked-first ordering -> idx/info.
//    One block (1024 threads) per batch row; 16 tokens/thread in registers.
// ======================================================================
__device__ __forceinline__ unsigned f2k(float f) {
    unsigned u = __float_as_uint(f);
    return (u & 0x80000000u) ? ~u : (u | 0x80000000u);
}

__global__ void select_kernel() {
    int a    = blockIdx.x;
    int tid  = threadIdx.x;
    int lane = tid & 31;
    int wid  = tid >> 5;

    unsigned kreg[16];
    const float4* wp = (const float4*)(g_w + (size_t)a * S_TOT + tid * 16);
#pragma unroll
    for (int i = 0; i < 4; i++) {
        float4 v = wp[i];
        kreg[i * 4 + 0] = f2k(v.x);
        kreg[i * 4 + 1] = f2k(v.y);
        kreg[i * 4 + 2] = f2k(v.z);
        kreg[i * 4 + 3] = f2k(v.w);
    }

    // --- binary search: largest u with count(key >= u) >= KSEL  (== k-th largest key) ---
    __shared__ int s_cnt;
    unsigned lo = 0u, hi = 0xFFFFFFFFu;
    while (lo < hi) {
        unsigned d   = hi - lo;
        unsigned mid = lo + (d >> 1) + (d & 1u);   // upper mid, overflow-safe
        __syncthreads();
        if (tid == 0) s_cnt = 0;
        __syncthreads();
        int c = 0;
#pragma unroll
        for (int i = 0; i < 16; i++) c += (kreg[i] >= mid);
#pragma unroll
        for (int o = 16; o > 0; o >>= 1) c += __shfl_down_sync(0xFFFFFFFFu, c, o);
        if (lane == 0) atomicAdd(&s_cnt, c);
        __syncthreads();
        if (s_cnt >= KSEL) lo = mid; else hi = mid - 1;
    }
    unsigned thr = lo;   // key of the k-th largest value

    // --- stable scan: masked (key > thr) tokens first, ascending t ---
    int m = 0;
#pragma unroll
    for (int i = 0; i < 16; i++) m += (kreg[i] > thr);

    int v = m;
#pragma unroll
    for (int d = 1; d < 32; d <<= 1) {
        int n = __shfl_up_sync(0xFFFFFFFFu, v, d);
        if (lane >= d) v += n;
    }
    __shared__ int wsum[32];
    __shared__ int s_mtot;
    if (lane == 31) wsum[wid] = v;
    __syncthreads();
    if (wid == 0) {
        int wv = wsum[lane];
#pragma unroll
        for (int d = 1; d < 32; d <<= 1) {
            int n = __shfl_up_sync(0xFFFFFFFFu, wv, d);
            if (lane >= d) wv += n;
        }
        wsum[lane] = wv;
        if (lane == 31) s_mtot = wv;
    }
    __syncthreads();

    int base = v - m + (wid ? wsum[wid - 1] : 0);  // masked tokens before this thread
    int mtot = s_mtot;                             // total masked (<= NSEL always)
    int run  = base;
    int t0   = tid * 16;
#pragma unroll
    for (int i = 0; i < 16; i++) {
        int  t  = t0 + i;
        bool mk = (kreg[i] > thr);
        int slot, info = 0;
        if (mk) { slot = run++; info = (int)0x80000000; }
        else    { slot = mtot + (t - run); }       // t - run = unmasked before t
        if (slot < NSEL) {
            g_idx[a * KSEL + slot] = t;
            info |= (slot + 1);
        }
        g_info[a * S_TOT + t] = info;
    }
}

// ======================================================================
// 3) Gather: blk_in[a][ic][slot] = x[a][ic][idx[slot]], slot NSEL.. = 0
//    grid (8, 256), 256 threads
// ======================================================================
__global__ void gather_kernel(const float* __restrict__ x) {
    int a = blockIdx.x, ic = blockIdx.y, tid = threadIdx.x;
    __shared__ int sidx[KSEL];
    for (int s = tid; s < KSEL; s += 256)
        sidx[s] = (s < NSEL) ? g_idx[a * KSEL + s] : -1;
    __syncthreads();

    const float* xr = x + ((size_t)a * C_N + ic) * S_TOT;
    float*       br = g_blkin + ((size_t)a * C_N + ic) * LPAD;
    for (int s = tid; s < KSEL; s += 256) {
        int t = sidx[s];
        br[s] = (t >= 0) ? xr[t] : 0.0f;
    }
}

// ======================================================================
// 4) Direct 3x3 SAME conv on (A, 256, 128, 16), fp32, register-tiled.
//    Block: 64 out-ch x (8 rows x 16 cols) spatial. ic chunks of 16.
//    grid (16, 4, 8), 256 threads, 50 KB dynamic smem.
// ======================================================================
#define OCT 64
#define ICC 16
#define WS_SZ      (ICC * 9 * OCT)       // 9216 floats
#define INS_RSTR   21                    // padded row stride (banks)
#define INS_ICSTR  (10 * INS_RSTR)       // 210
#define INS_SZ     (ICC * INS_ICSTR)     // 3360 floats
#define CONV_SMEM  ((WS_SZ + INS_SZ) * 4)

__global__ void __launch_bounds__(256) conv_kernel(const float* __restrict__ bw,
                                                   const float* __restrict__ bb) {
    extern __shared__ float sm[];
    float* ws  = sm;           // [ic*9+k][oc]  (k-major x oc)
    float* ins = sm + WS_SZ;   // [ic][row 0..9][col 0..17] (halo + zero pad)

    int tid   = threadIdx.x;
    int a     = blockIdx.z;
    int oc0   = blockIdx.y * OCT;
    int r0    = blockIdx.x * 8;
    int tg_oc = tid >> 5;            // warp id -> 8 output channels (broadcast LDS)
    int lane  = tid & 31;
    int rl    = lane >> 2;           // row within tile 0..7
    int c0    = (lane & 3) * 4;      // col group 0,4,8,12

    float acc[8][4];
#pragma unroll
    for (int o = 0; o < 8; o++)
#pragma unroll
        for (int j = 0; j < 4; j++) acc[o][j] = 0.f;

    const float* bin = g_blkin + (size_t)a * C_N * LPAD;

    for (int ic0 = 0; ic0 < C_N; ic0 += ICC) {
        // weights: bw[oc][ic][3][3], ic-chunk contiguous per oc (144 floats)
        for (int i = tid; i < WS_SZ; i += 256) {
            int oc = i / (ICC * 9);
            int r  = i - oc * (ICC * 9);
            ws[r * OCT + oc] = bw[(size_t)(oc0 + oc) * (C_N * 9) + ic0 * 9 + r];
        }
        // input halo tile: rows r0-1..r0+8, cols -1..16, zero padded
        for (int i = tid; i < ICC * 10 * 18; i += 256) {
            int ic  = i / 180;
            int rem = i - ic * 180;
            int row = rem / 18;
            int cc  = rem - row * 18;
            int gh  = r0 + row - 1;
            int gw  = cc - 1;
            float v = 0.f;
            if (gh >= 0 && gh < HH && gw >= 0 && gw < WW)
                v = bin[(size_t)(ic0 + ic) * LPAD + gh * WW + gw];
            ins[ic * INS_ICSTR + row * INS_RSTR + cc] = v;
        }
        __syncthreads();

#pragma unroll 2
        for (int ic = 0; ic < ICC; ic++) {
#pragma unroll
            for (int kh = 0; kh < 3; kh++) {
                float iv[6];
                const float* ir = ins + ic * INS_ICSTR + (rl + kh) * INS_RSTR + c0;
#pragma unroll
                for (int j = 0; j < 6; j++) iv[j] = ir[j];
#pragma unroll
                for (int kw = 0; kw < 3; kw++) {
                    const float* wr = ws + (ic * 9 + kh * 3 + kw) * OCT + tg_oc * 8;
                    float4 wa = *(const float4*)wr;
                    float4 wb = *(const float4*)(wr + 4);
                    float w8[8] = {wa.x, wa.y, wa.z, wa.w, wb.x, wb.y, wb.z, wb.w};
#pragma unroll
                    for (int o = 0; o < 8; o++)
#pragma unroll
                        for (int j = 0; j < 4; j++)
                            acc[o][j] += w8[o] * iv[kw + j];
                }
            }
        }
        __syncthreads();
    }

    float* co = g_convout + (size_t)a * C_N * LPAD;
    int sp = (r0 + rl) * WW + c0;
#pragma unroll
    for (int o = 0; o < 8; o++) {
        int oc = oc0 + tg_oc * 8 + o;
        float bias = bb[oc];
        float4 v = make_float4(acc[o][0] + bias, acc[o][1] + bias,
                               acc[o][2] + bias, acc[o][3] + bias);
        *(float4*)(co + (size_t)oc * LPAD + sp) = v;
    }
}

// ======================================================================
// 5) Combine: out[a][c][t] = (selected ? conv_out[a][c][slot] : 0)
//                          + (masked ? 0 : x[a][c][t])
//    grid (64, 8), 256 threads; coalesced over t per channel.
// ======================================================================
__global__ void combine_kernel(const float* __restrict__ x, float* __restrict__ out) {
    int a = blockIdx.y;
    int t = blockIdx.x * 256 + threadIdx.x;

    int info    = g_info[a * S_TOT + t];
    int slotp   = info & 0xFFFF;                   // slot+1, 0 = not selected
    bool masked = (info & 0x80000000) != 0;

    const float* xr = x         + (size_t)a * C_N * S_TOT + t;
    const float* cr = g_convout + (size_t)a * C_N * LPAD  + (slotp - 1);
    float*       orow = out     + (size_t)a * C_N * S_TOT + t;

#pragma unroll 4
    for (int c = 0; c < C_N; c++) {
        float v = 0.f;
        if (slotp)   v  = cr[(size_t)c * LPAD];
        if (!masked) v += xr[(size_t)c * S_TOT];
        orow[(size_t)c * S_TOT] = v;
    }
}

// ======================================================================
extern "C" void kernel_launch(void* const* d_in, const int* in_sizes, int n_in,
                              void* d_out, int out_size) {
    const float* x  = (const float*)d_in[0];
    const float* rw = (const float*)d_in[1];
    const float* rb = (const float*)d_in[2];
    const float* bw = (const float*)d_in[3];
    const float* bb = (const float*)d_in[4];
    float* out = (float*)d_out;

    cudaFuncSetAttribute(conv_kernel, cudaFuncAttributeMaxDynamicSharedMemorySize, CONV_SMEM);

    dim3 rg(S_TOT / (256 * 4), A_N);          // (16, 8)
    router_kernel<<<rg, 256>>>(x, rw, rb);

    select_kernel<<<A_N, 1024>>>();

    dim3 gg(A_N, C_N);                        // (8, 256)
    gather_kernel<<<gg, 256>>>(x);

    dim3 cg(HH / 8, C_N / OCT, A_N);          // (16, 4, 8)
    conv_kernel<<<cg, 256, CONV_SMEM>>>(bw, bb);

    dim3 mg(S_TOT / 256, A_N);                // (64, 8)
    combine_kernel<<<mg, 256>>>(x, out);
}

// round 3
// speedup vs baseline: 1.9345x; 1.9345x over previous
#include <cuda_runtime.h>
#include <cuda_bf16.h>
#include <cstdint>

// ---------------- problem constants ----------------
#define A_N   8
#define C_N   256
#define S_TOT 16384
#define KSEL  2048
#define NSEL  2047
#define LPAD  2048
#define HH    128
#define WW    16
#define KTOT  2304            // 256 ic * 9

// ---------------- device scratch ----------------
__device__ float    g_w[A_N * S_TOT];
__device__ int      g_idx[A_N * KSEL];
__device__ int      g_info[A_N * S_TOT];
__device__ __align__(16) uint32_t      g_bpk[A_N * C_N * LPAD];  // bf16 hi|lo<<16 of gathered input
__device__ __align__(16) __nv_bfloat16 g_whi[C_N * KTOT];        // weight hi, [oc][k]
__device__ __align__(16) __nv_bfloat16 g_wlo[C_N * KTOT];        // weight lo
__device__ float    g_convout[A_N * C_N * LPAD];

// ---------------- helpers ----------------
__device__ __forceinline__ uint32_t smem_u32(const void* p) {
    uint32_t a;
    asm("{ .reg .u64 t; cvta.to.shared.u64 t, %1; cvt.u32.u64 %0, t; }" : "=r"(a) : "l"(p));
    return a;
}
__device__ __forceinline__ void ldsm4(uint32_t* r, uint32_t addr) {
    asm volatile("ldmatrix.sync.aligned.m8n8.x4.shared.b16 {%0,%1,%2,%3}, [%4];"
                 : "=r"(r[0]), "=r"(r[1]), "=r"(r[2]), "=r"(r[3]) : "r"(addr));
}
__device__ __forceinline__ void ldsm4t(uint32_t* r, uint32_t addr) {
    asm volatile("ldmatrix.sync.aligned.m8n8.x4.trans.shared.b16 {%0,%1,%2,%3}, [%4];"
                 : "=r"(r[0]), "=r"(r[1]), "=r"(r[2]), "=r"(r[3]) : "r"(addr));
}
__device__ __forceinline__ void mma16816(float* d, const uint32_t* a, uint32_t b0, uint32_t b1) {
    asm volatile(
        "mma.sync.aligned.m16n8k16.row.col.f32.bf16.bf16.f32 "
        "{%0,%1,%2,%3}, {%4,%5,%6,%7}, {%8,%9}, {%0,%1,%2,%3};"
        : "+f"(d[0]), "+f"(d[1]), "+f"(d[2]), "+f"(d[3])
        : "r"(a[0]), "r"(a[1]), "r"(a[2]), "r"(a[3]), "r"(b0), "r"(b1));
}

// ======================================================================
// 1) Router
// ======================================================================
__global__ void router_kernel(const float* __restrict__ x,
                              const float* __restrict__ rw,
                              const float* __restrict__ rb) {
    __shared__ float srw[C_N];
    int tid = threadIdx.x;
    srw[tid] = rw[tid];
    __syncthreads();
    int a  = blockIdx.y;
    int t0 = (blockIdx.x * 256 + tid) * 4;
    const float4* xp = (const float4*)(x + (size_t)a * C_N * S_TOT + t0);
    float4 acc = make_float4(0.f, 0.f, 0.f, 0.f);
#pragma unroll 8
    for (int c = 0; c < C_N; c++) {
        float4 v = xp[(size_t)c * (S_TOT / 4)];
        float wv = srw[c];
        acc.x += v.x * wv; acc.y += v.y * wv;
        acc.z += v.z * wv; acc.w += v.w * wv;
    }
    float b = rb[0];
    *(float4*)(g_w + (size_t)a * S_TOT + t0) =
        make_float4(acc.x + b, acc.y + b, acc.z + b, acc.w + b);
}

// ======================================================================
// 2) Select (exact k-th largest + stable masked-first order)
// ======================================================================
__device__ __forceinline__ unsigned f2k(float f) {
    unsigned u = __float_as_uint(f);
    return (u & 0x80000000u) ? ~u : (u | 0x80000000u);
}

__global__ void select_kernel() {
    int a = blockIdx.x, tid = threadIdx.x, lane = tid & 31, wid = tid >> 5;
    unsigned kreg[16];
    const float4* wp = (const float4*)(g_w + (size_t)a * S_TOT + tid * 16);
#pragma unroll
    for (int i = 0; i < 4; i++) {
        float4 v = wp[i];
        kreg[i*4+0] = f2k(v.x); kreg[i*4+1] = f2k(v.y);
        kreg[i*4+2] = f2k(v.z); kreg[i*4+3] = f2k(v.w);
    }
    __shared__ int s_cnt;
    unsigned lo = 0u, hi = 0xFFFFFFFFu;
    while (lo < hi) {
        unsigned d = hi - lo;
        unsigned mid = lo + (d >> 1) + (d & 1u);
        __syncthreads();
        if (tid == 0) s_cnt = 0;
        __syncthreads();
        int c = 0;
#pragma unroll
        for (int i = 0; i < 16; i++) c += (kreg[i] >= mid);
#pragma unroll
        for (int o = 16; o > 0; o >>= 1) c += __shfl_down_sync(0xFFFFFFFFu, c, o);
        if (lane == 0) atomicAdd(&s_cnt, c);
        __syncthreads();
        if (s_cnt >= KSEL) lo = mid; else hi = mid - 1;
    }
    unsigned thr = lo;

    int m = 0;
#pragma unroll
    for (int i = 0; i < 16; i++) m += (kreg[i] > thr);
    int v = m;
#pragma unroll
    for (int d = 1; d < 32; d <<= 1) {
        int n = __shfl_up_sync(0xFFFFFFFFu, v, d);
        if (lane >= d) v += n;
    }
    __shared__ int wsum[32];
    __shared__ int s_mtot;
    if (lane == 31) wsum[wid] = v;
    __syncthreads();
    if (wid == 0) {
        int wv = wsum[lane];
#pragma unroll
        for (int d = 1; d < 32; d <<= 1) {
            int n = __shfl_up_sync(0xFFFFFFFFu, wv, d);
            if (lane >= d) wv += n;
        }
        wsum[lane] = wv;
        if (lane == 31) s_mtot = wv;
    }
    __syncthreads();
    int base = v - m + (wid ? wsum[wid - 1] : 0);
    int mtot = s_mtot;
    int run = base, t0 = tid * 16;
#pragma unroll
    for (int i = 0; i < 16; i++) {
        int t = t0 + i;
        bool mk = (kreg[i] > thr);
        int slot, info = 0;
        if (mk) { slot = run++; info = (int)0x80000000; }
        else    { slot = mtot + (t - run); }
        if (slot < NSEL) {
            g_idx[a * KSEL + slot] = t;
            info |= (slot + 1);
        }
        g_info[a * S_TOT + t] = info;
    }
}

// ======================================================================
// 3) Gather + bf16 hi/lo split pack
// ======================================================================
__device__ __forceinline__ uint32_t splitpack(float v) {
    __nv_bfloat16 h = __float2bfloat16(v);
    float hf = __bfloat162float(h);
    __nv_bfloat16 l = __float2bfloat16(v - hf);
    return (uint32_t)__bfloat16_as_ushort(h) | ((uint32_t)__bfloat16_as_ushort(l) << 16);
}

__global__ void gather_kernel(const float* __restrict__ x) {
    int a = blockIdx.x, ic = blockIdx.y, tid = threadIdx.x;
    __shared__ int sidx[KSEL];
    for (int s = tid; s < KSEL; s += 256)
        sidx[s] = (s < NSEL) ? g_idx[a * KSEL + s] : -1;
    __syncthreads();
    const float* xr = x + ((size_t)a * C_N + ic) * S_TOT;
    uint32_t*    br = g_bpk + ((size_t)a * C_N + ic) * LPAD;
    for (int s = tid; s < KSEL; s += 256) {
        int t = sidx[s];
        float v = (t >= 0) ? xr[t] : 0.0f;
        br[s] = splitpack(v);
    }
}

// ======================================================================
// 3b) Weight split: g_whi/g_wlo[oc*KTOT + k]
// ======================================================================
__global__ void wprep_kernel(const float* __restrict__ bw) {
    int idx = blockIdx.x * 256 + threadIdx.x;
    float v = bw[idx];
    __nv_bfloat16 h = __float2bfloat16(v);
    g_whi[idx] = h;
    g_wlo[idx] = __float2bfloat16(v - __bfloat162float(h));
}

// ======================================================================
// 4) Conv as implicit GEMM via mma.sync bf16x3, fp32 accum
//    CTA 128m x 128n, 8 warps (2x4) each 64x32, K chunks of 32.
// ======================================================================
#define SA_STRIDE_B 80       // 32 bf16 data + pad, bytes
#define SB_STRIDE_B 272      // 128 bf16 data + pad, bytes
#define OFF_AHI 0
#define OFF_ALO 10240
#define OFF_BHI 20480
#define OFF_BLO 29184
#define BUF_BYTES 37888
#define CONV_SMEM (2 * BUF_BYTES)
#define NCHUNK 72

__global__ void __launch_bounds__(256) conv_mma_kernel(const float* __restrict__ bb) {
    extern __shared__ char sm[];
    uint32_t sbase = smem_u32(sm);

    int tid  = threadIdx.x;
    int lane = tid & 31, wid = tid >> 5;
    int wm = wid >> 2, wn = wid & 3;           // 2 x 4 warp grid
    int n0 = blockIdx.x * 128;
    int m0 = blockIdx.y * 128;
    int a  = blockIdx.z;

    // ---- B (im2col) thread invariants: thread owns k-row kl, cols nl..nl+15 ----
    int kl = tid >> 3;                // 0..31
    int nl = (tid & 7) * 16;          // 0..112
    const uint32_t* bbase = g_bpk + (size_t)a * C_N * LPAD;

    // ---- A copy invariants: thread owns weight row am, k half ak ----
    int am = tid >> 1;
    int ak = (tid & 1) * 16;
    const __nv_bfloat16* whi = g_whi + (size_t)(m0 + am) * KTOT + ak;
    const __nv_bfloat16* wlo = g_wlo + (size_t)(m0 + am) * KTOT + ak;

    // ldmatrix lane offsets
    uint32_t a_loff = (uint32_t)((lane & 15) * SA_STRIDE_B + (lane >> 4) * 16);
    uint32_t b_loff = (uint32_t)(((lane & 7) + ((lane >> 3) & 1) * 8) * SB_STRIDE_B + (lane >> 4) * 16);

    float acc[4][4][4];
#pragma unroll
    for (int mt = 0; mt < 4; mt++)
#pragma unroll
        for (int j = 0; j < 4; j++)
#pragma unroll
            for (int e = 0; e < 4; e++) acc[mt][j][e] = 0.f;

    uint32_t breg[16];
    uint4 ahr0, ahr1, alr0, alr1;

    // ---------- load chunk i into regs ----------
    auto load_chunk = [&](int i) {
        const uint4* ph = (const uint4*)(whi + i * 32);
        const uint4* pl = (const uint4*)(wlo + i * 32);
        ahr0 = ph[0]; ahr1 = ph[1];
        alr0 = pl[0]; alr1 = pl[1];
        int kg = i * 32 + kl;
        int ic = kg / 9;
        int r  = kg - ic * 9;
        int dh = r / 3 - 1;
        int dw = (r - (r / 3) * 3) - 1;
        const uint32_t* src = bbase + (size_t)ic * LPAD + dh * 16 + dw;
#pragma unroll
        for (int j = 0; j < 16; j++) {
            int n_g = n0 + nl + j;
            int h = n_g >> 4, w = n_g & 15;
            bool ok = ((unsigned)(h + dh) < HH) && ((unsigned)(w + dw) < WW);
            breg[j] = ok ? src[n_g] : 0u;
        }
    };
    // ---------- store regs into smem buffer ----------
    auto store_chunk = [&](int buf) {
        char* bd = sm + buf * BUF_BYTES;
        uint32_t ao = OFF_AHI + am * SA_STRIDE_B + ak * 2;
        *(uint4*)(bd + ao)      = ahr0;
        *(uint4*)(bd + ao + 16) = ahr1;
        uint32_t ao2 = OFF_ALO + am * SA_STRIDE_B + ak * 2;
        *(uint4*)(bd + ao2)      = alr0;
        *(uint4*)(bd + ao2 + 16) = alr1;
        uint32_t bh = OFF_BHI + kl * SB_STRIDE_B + nl * 2;
        uint32_t bl = OFF_BLO + kl * SB_STRIDE_B + nl * 2;
#pragma unroll
        for (int j = 0; j < 16; j += 2) {
            uint32_t hip = (breg[j] & 0xFFFFu) | (breg[j + 1] << 16);
            uint32_t lop = (breg[j] >> 16) | (breg[j + 1] & 0xFFFF0000u);
            *(uint32_t*)(bd + bh + j * 2) = hip;
            *(uint32_t*)(bd + bl + j * 2) = lop;
        }
    };

    load_chunk(0);
    store_chunk(0);
    __syncthreads();

    for (int i = 0; i < NCHUNK; i++) {
        int cur = i & 1;
        if (i + 1 < NCHUNK) load_chunk(i + 1);

        uint32_t sb  = sbase + cur * BUF_BYTES;
        uint32_t aHi = sb + OFF_AHI + wm * 64 * SA_STRIDE_B + a_loff;
        uint32_t aLo = sb + OFF_ALO + wm * 64 * SA_STRIDE_B + a_loff;
        uint32_t bHi = sb + OFF_BHI + wn * 64 + b_loff;     // wn*32 cols * 2B
        uint32_t bLo = sb + OFF_BLO + wn * 64 + b_loff;

#pragma unroll
        for (int ks = 0; ks < 2; ks++) {
            uint32_t ah[4][4], al[4][4], bh[2][4], bl2[2][4];
#pragma unroll
            for (int mt = 0; mt < 4; mt++) {
                ldsm4(ah[mt], aHi + ks * 32 + mt * (16 * SA_STRIDE_B));
                ldsm4(al[mt], aLo + ks * 32 + mt * (16 * SA_STRIDE_B));
            }
#pragma unroll
            for (int g = 0; g < 2; g++) {
                ldsm4t(bh[g],  bHi + ks * (16 * SB_STRIDE_B) + g * 32);
                ldsm4t(bl2[g], bLo + ks * (16 * SB_STRIDE_B) + g * 32);
            }
#pragma unroll
            for (int mt = 0; mt < 4; mt++)
#pragma unroll
                for (int j = 0; j < 4; j++) {
                    int g = j >> 1, h2 = (j & 1) * 2;
                    mma16816(acc[mt][j], ah[mt], bh[g][h2], bh[g][h2 + 1]);
                    mma16816(acc[mt][j], al[mt], bh[g][h2], bh[g][h2 + 1]);
                    mma16816(acc[mt][j], ah[mt], bl2[g][h2], bl2[g][h2 + 1]);
                }
        }
        if (i + 1 < NCHUNK) store_chunk(1 - cur);
        __syncthreads();
    }

    // ---------- epilogue ----------
    float* dst = g_convout + (size_t)a * C_N * LPAD;
#pragma unroll
    for (int mt = 0; mt < 4; mt++) {
        int r0 = m0 + wm * 64 + mt * 16 + (lane >> 2);
        float b0v = bb[r0], b1v = bb[r0 + 8];
#pragma unroll
        for (int j = 0; j < 4; j++) {
            int col = n0 + wn * 32 + j * 8 + (lane & 3) * 2;
            float2 v0 = make_float2(acc[mt][j][0] + b0v, acc[mt][j][1] + b0v);
            float2 v1 = make_float2(acc[mt][j][2] + b1v, acc[mt][j][3] + b1v);
            *(float2*)(dst + (size_t)r0 * LPAD + col)       = v0;
            *(float2*)(dst + (size_t)(r0 + 8) * LPAD + col) = v1;
        }
    }
}

// ======================================================================
// 5) Combine
// ======================================================================
__global__ void combine_kernel(const float* __restrict__ x, float* __restrict__ out) {
    int a = blockIdx.y;
    int t = blockIdx.x * 256 + threadIdx.x;
    int info  = g_info[a * S_TOT + t];
    int slotp = info & 0xFFFF;
    bool masked = (info & 0x80000000) != 0;
    const float* xr = x + (size_t)a * C_N * S_TOT + t;
    const float* cr = g_convout + (size_t)a * C_N * LPAD + (slotp - 1);
    float* orow = out + (size_t)a * C_N * S_TOT + t;
#pragma unroll 4
    for (int c = 0; c < C_N; c++) {
        float v = 0.f;
        if (slotp)   v  = cr[(size_t)c * LPAD];
        if (!masked) v += xr[(size_t)c * S_TOT];
        orow[(size_t)c * S_TOT] = v;
    }
}

// ======================================================================
extern "C" void kernel_launch(void* const* d_in, const int* in_sizes, int n_in,
                              void* d_out, int out_size) {
    const float* x  = (const float*)d_in[0];
    const float* rw = (const float*)d_in[1];
    const float* rb = (const float*)d_in[2];
    const float* bw = (const float*)d_in[3];
    const float* bb = (const float*)d_in[4];
    float* out = (float*)d_out;

    cudaFuncSetAttribute(conv_mma_kernel, cudaFuncAttributeMaxDynamicSharedMemorySize, CONV_SMEM);

    dim3 rg(S_TOT / (256 * 4), A_N);
    router_kernel<<<rg, 256>>>(x, rw, rb);

    wprep_kernel<<<(C_N * KTOT) / 256, 256>>>(bw);

    select_kernel<<<A_N, 1024>>>();

    dim3 gg(A_N, C_N);
    gather_kernel<<<gg, 256>>>(x);

    dim3 cg(16, 2, A_N);
    conv_mma_kernel<<<cg, 256, CONV_SMEM>>>(bb);

    dim3 mg(S_TOT / 256, A_N);
    combine_kernel<<<mg, 256>>>(x, out);
}